// round 14
// baseline (speedup 1.0000x reference)
#include <cuda_runtime.h>
#include <cuda_bf16.h>
#include <cstdint>

#define BB 256   // batch
#define TT 512   // encoder steps
#define FF 64    // input features
#define HH 1024  // hidden
#define TLEN 64  // decoder steps
#define N3 3072  // 3*H output columns (gate-interleaved)
#define KK 3072  // augmented K: [h_hi | h_lo | h_hi]
#define NC 48    // K chunks of 64
#define NSTG 4   // pipeline stages (power of 2)

#define A_TILE_B 4096           // h tile: 32 rows x 128B (SW128)
#define B_TILE_B 6144           // W tile: 48 rows x 128B
#define STAGE_B  (A_TILE_B + B_TILE_B)   // 10240
#define HDR 1024
#define SMEMSZ (HDR + NSTG * STAGE_B)    // 41984  -> 4 CTAs/SM

__device__ __forceinline__ uint32_t sw128(uint32_t off) { return off ^ ((off >> 3) & 0x70); }

// ---------------- device scratch (static globals; no allocation) ----------------
// Weights as contiguous pre-swizzled tiles: [2][64 nb][48 c][48*64]
__device__ __align__(128) __nv_bfloat16 g_Wt[2][64][NC][48 * 64];
// h as contiguous pre-swizzled tiles: [2 par][8 mb][48 c][32*64]
__device__ __align__(128) __nv_bfloat16 g_ht[2][8][NC][32 * 64];
__device__ float g_bih_e[N3], g_bhh_e[N3], g_bih_d[N3], g_bhh_d[N3]; // permuted biases
__device__ float g_Wihp_e[(size_t)HH * 192];            // enc W_ih, per-unit [r|z|n]
__device__ float g_Wih_d[N3];                           // dec W_ih (scalar input), permuted

// ---------------- PTX helpers ----------------
__device__ __forceinline__ void ldsm_x4(uint32_t* r, uint32_t addr) {
    asm volatile("ldmatrix.sync.aligned.m8n8.x4.shared.b16 {%0,%1,%2,%3}, [%4];"
                 : "=r"(r[0]), "=r"(r[1]), "=r"(r[2]), "=r"(r[3]) : "r"(addr));
}
__device__ __forceinline__ void ldsm_x2(uint32_t* r, uint32_t addr) {
    asm volatile("ldmatrix.sync.aligned.m8n8.x2.shared.b16 {%0,%1}, [%2];"
                 : "=r"(r[0]), "=r"(r[1]) : "r"(addr));
}
__device__ __forceinline__ void mma_bf16(float* c, const uint32_t* a, uint32_t b0, uint32_t b1) {
    asm volatile("mma.sync.aligned.m16n8k16.row.col.f32.bf16.bf16.f32 "
                 "{%0,%1,%2,%3}, {%4,%5,%6,%7}, {%8,%9}, {%0,%1,%2,%3};"
                 : "+f"(c[0]), "+f"(c[1]), "+f"(c[2]), "+f"(c[3])
                 : "r"(a[0]), "r"(a[1]), "r"(a[2]), "r"(a[3]), "r"(b0), "r"(b1));
}
__device__ __forceinline__ void mbar_init(uint32_t mbar, uint32_t cnt) {
    asm volatile("mbarrier.init.shared.b64 [%0], %1;" :: "r"(mbar), "r"(cnt) : "memory");
}
__device__ __forceinline__ void mbar_expect_tx(uint32_t mbar, uint32_t bytes) {
    asm volatile("mbarrier.arrive.expect_tx.shared.b64 _, [%0], %1;"
                 :: "r"(mbar), "r"(bytes) : "memory");
}
__device__ __forceinline__ void mbar_wait(uint32_t mbar, uint32_t parity) {
    asm volatile(
        "{\n\t.reg .pred P1;\n\t"
        "WL_%=:\n\t"
        "mbarrier.try_wait.parity.acquire.cta.shared::cta.b64 P1, [%0], %1, 0x989680;\n\t"
        "@P1 bra.uni WD_%=;\n\t"
        "bra.uni WL_%=;\n\t"
        "WD_%=:\n\t}"
        :: "r"(mbar), "r"(parity) : "memory");
}
__device__ __forceinline__ void bulk_g2s(uint32_t dst, const void* src, uint32_t bytes, uint32_t mbar) {
    asm volatile("cp.async.bulk.shared::cluster.global.mbarrier::complete_tx::bytes "
                 "[%0], [%1], %2, [%3];"
                 :: "r"(dst), "l"(src), "r"(bytes), "r"(mbar) : "memory");
}

// ---------------- prep: tiled, swizzled, augmented, gate-interleaved weights ----------------
__global__ void prep_weights(const float* __restrict__ encW, const float* __restrict__ decW) {
    size_t idx = (size_t)blockIdx.x * blockDim.x + threadIdx.x;
    const size_t one = (size_t)N3 * KK;
    if (idx >= 2 * one) return;
    int which = idx >= one;
    size_t rem = which ? idx - one : idx;
    int j = (int)(rem / KK);
    int k = (int)(rem % KK);
    int u = j / 3, g = j - 3 * u;
    const float* W = which ? decW : encW;
    float w = W[(size_t)(g * HH + u) * HH + (k & 1023)];
    __nv_bfloat16 hi = __float2bfloat16(w);
    __nv_bfloat16 out = (k < 2048) ? hi : __float2bfloat16(w - __bfloat162float(hi));
    int nb = j / 48, jr = j - nb * 48;
    int c = k >> 6, kk = k & 63;
    uint32_t swb = sw128((uint32_t)(jr * 128 + kk * 2));
    g_Wt[which][nb][c][swb >> 1] = out;
}

// ---------------- prep: biases, permuted W_ih, zero h tiles, init d_out = fc_b ----------------
__global__ void prep_misc(const float* __restrict__ ebih, const float* __restrict__ ebhh,
                          const float* __restrict__ dbih, const float* __restrict__ dbhh,
                          const float* __restrict__ eWih, const float* __restrict__ dWih,
                          const float* __restrict__ fcb, float* __restrict__ dout) {
    int tid = blockIdx.x * blockDim.x + threadIdx.x;
    int stride = gridDim.x * blockDim.x;
    for (int i = tid; i < N3; i += stride) {
        int u = i / 3, g = i - 3 * u;
        int o = g * HH + u;
        g_bih_e[i] = ebih[o];
        g_bhh_e[i] = ebhh[o];
        g_bih_d[i] = dbih[o];
        g_bhh_d[i] = dbhh[o];
        g_Wih_d[i] = dWih[o];
    }
    for (int i = tid; i < HH * 192; i += stride) {
        int u = i / 192, rem = i - u * 192;
        int g = rem >> 6, f = rem & 63;
        g_Wihp_e[i] = eWih[(size_t)(g * HH + u) * FF + f];
    }
    const int nh = 2 * 8 * NC * 32 * 64 / 2;    // u32 words over both h buffers
    for (int i = tid; i < nh; i += stride) ((uint32_t*)g_ht)[i] = 0u;
    for (int i = tid; i < BB * TLEN; i += stride) dout[i] = fcb[0];
}

// ---------------- one recurrent step: 4-CTA/SM bulk-fed GEMM + fused GRU epilogue ----------------
// grid (64, 8): blockIdx.x = 48-col tile (16 units), blockIdx.y = 32-row batch tile.
// 128 threads, 4 warps as 2(M) x 2(N), warp tile 16x24.
__global__ __launch_bounds__(128, 4) void gru_step_kernel(
    int t, int mode, int par,
    const float* __restrict__ x, const float* __restrict__ fcW, float* __restrict__ dout)
{
    const float* __restrict__ bih = mode ? g_bih_d : g_bih_e;
    const float* __restrict__ bhh = mode ? g_bhh_d : g_bhh_e;

    extern __shared__ __align__(16) unsigned char smem_raw[];
    const int tid = threadIdx.x;
    const int lane = tid & 31, warp = tid >> 5;
    const int wm = warp >> 1, wn = warp & 1;     // 2 x 2 warps -> 16x24 warp tiles
    const int nb = blockIdx.x, mb = blockIdx.y;

    const uint32_t smBase = (uint32_t)__cvta_generic_to_shared(smem_raw);
    const uint32_t mbar0 = smBase;               // 4 mbarriers x 8B in header
    const uint32_t smData = smBase + HDR;

    const __nv_bfloat16* __restrict__ Asrc = &g_ht[par][mb][0][0];
    const __nv_bfloat16* __restrict__ Bsrc = &g_Wt[mode][nb][0][0];
    __nv_bfloat16* __restrict__ hdst = &g_ht[par ^ 1][mb][0][0];
    const __nv_bfloat16* __restrict__ hsrc = Asrc;

    if (tid == 0) {
        #pragma unroll
        for (int s = 0; s < NSTG; s++) mbar_init(mbar0 + 8 * s, 1);
    }
    __syncthreads();

    auto issue = [&](int c) {
        const int s = c & (NSTG - 1);
        const uint32_t mb_ = mbar0 + 8 * s;
        mbar_expect_tx(mb_, STAGE_B);
        const uint32_t d = smData + s * STAGE_B;
        bulk_g2s(d,            Asrc + (size_t)c * 2048, A_TILE_B, mb_);
        bulk_g2s(d + A_TILE_B, Bsrc + (size_t)c * 3072, B_TILE_B, mb_);
    };

    if (tid == 0) {
        #pragma unroll
        for (int s = 0; s < NSTG - 1; s++) issue(s);
    }

    float acc[3][4];
    #pragma unroll
    for (int ni = 0; ni < 3; ni++)
        #pragma unroll
        for (int q = 0; q < 4; q++) acc[ni][q] = 0.f;

    for (int c = 0; c < NC; c++) {
        __syncthreads();                          // previous stage slot drained by all warps
        if (tid == 0 && c + NSTG - 1 < NC) issue(c + NSTG - 1);
        mbar_wait(mbar0 + 8 * (c & (NSTG - 1)), (c >> 2) & 1);

        const uint32_t sA = smData + (c & (NSTG - 1)) * STAGE_B;
        const uint32_t sB = sA + A_TILE_B;
        #pragma unroll
        for (int ks = 0; ks < 4; ks++) {
            uint32_t ra[4], rb4[4], rb2[2];
            {   // A m16k16 (rows wm*16 .. +15)
                uint32_t off = (uint32_t)((wm * 16 + (lane & 15)) * 128
                                          + ks * 32 + (lane >> 4) * 16);
                ldsm_x4(ra, sA + sw128(off));
            }
            {   // B n16k16 via one x4 (rows wn*24 .. +15)
                uint32_t off = (uint32_t)((wn * 24 + (lane & 15)) * 128
                                          + ks * 32 + (lane >> 4) * 16);
                ldsm_x4(rb4, sB + sw128(off));
            }
            {   // B n8k16 via x2 (rows wn*24+16 .. +23)
                uint32_t off = (uint32_t)((wn * 24 + 16 + (lane & 7)) * 128
                                          + ks * 32 + ((lane >> 3) & 1) * 16);
                ldsm_x2(rb2, sB + sw128(off));
            }
            // x4 B reg order: {n0-7 k0-7, n8-15 k0-7, n0-7 k8-15, n8-15 k8-15}
            mma_bf16(acc[0], ra, rb4[0], rb4[2]);
            mma_bf16(acc[1], ra, rb4[1], rb4[3]);
            mma_bf16(acc[2], ra, rb2[0], rb2[1]);
        }
    }

    // ---- stage accumulators to smem (reuse data region) ----
    __syncthreads();
    float* Csm = (float*)(smem_raw + HDR);               // 32 x 48, pitch 51 (6528 B)
    float* Xs  = (float*)(smem_raw + HDR + 6656);        // 32 x 64 floats (8192 B)
    #pragma unroll
    for (int ni = 0; ni < 3; ni++) {
        int m = wm * 16 + (lane >> 2);
        int n = wn * 24 + ni * 8 + ((lane & 3) << 1);
        Csm[m * 51 + n]           = acc[ni][0];
        Csm[m * 51 + n + 1]       = acc[ni][1];
        Csm[(m + 8) * 51 + n]     = acc[ni][2];
        Csm[(m + 8) * 51 + n + 1] = acc[ni][3];
    }
    if (mode == 0) {
        #pragma unroll
        for (int q = 0; q < 4; q++) {
            int id = tid + q * 128;
            int r = id >> 4, c4 = id & 15;
            ((float4*)Xs)[r * 16 + c4] =
                *(const float4*)(x + ((size_t)(mb * 32 + r) * TT + t) * FF + c4 * 4);
        }
    }
    __syncthreads();

    // ---- fused GRU epilogue: each thread owns (batch row bl, 4 hidden units) ----
    const int bl = tid >> 2, uq = tid & 3;
    const int b = mb * 32 + bl;
    float inp = 0.f;
    if (mode && t > 0) inp = dout[b * TLEN + (t - 1)];
    float fcsum = 0.f;
    const float4* xs4 = (const float4*)(Xs + bl * 64);

    #pragma unroll
    for (int i = 0; i < 4; i++) {
        int ul = uq * 4 + i;
        int u = nb * 16 + ul;
        float ar = Csm[bl * 51 + ul * 3 + 0];
        float az = Csm[bl * 51 + ul * 3 + 1];
        float an = Csm[bl * 51 + ul * 3 + 2];
        float gr, gz, gn;
        if (mode == 0) {
            gr = gz = gn = 0.f;
            const float4* wr4 = (const float4*)(g_Wihp_e + (size_t)u * 192);
            #pragma unroll
            for (int q = 0; q < 16; q++) {
                float4 xv = xs4[q];
                float4 a = wr4[q], bq = wr4[16 + q], cq = wr4[32 + q];
                gr += xv.x * a.x + xv.y * a.y + xv.z * a.z + xv.w * a.w;
                gz += xv.x * bq.x + xv.y * bq.y + xv.z * bq.z + xv.w * bq.w;
                gn += xv.x * cq.x + xv.y * cq.y + xv.z * cq.z + xv.w * cq.w;
            }
        } else {
            gr = inp * g_Wih_d[u * 3 + 0];
            gz = inp * g_Wih_d[u * 3 + 1];
            gn = inp * g_Wih_d[u * 3 + 2];
        }
        // hprev = h_hi (chunk u>>6) + h_lo (chunk 16 + u>>6), swizzled tile layout
        const int kk2 = (u & 63) * 2;
        const uint32_t swo = sw128((uint32_t)(bl * 128 + kk2));
        float hp_hi = __bfloat162float(
            *(const __nv_bfloat16*)((const char*)hsrc + (size_t)(u >> 6) * A_TILE_B + swo));
        float hp_lo = __bfloat162float(
            *(const __nv_bfloat16*)((const char*)hsrc + (size_t)(16 + (u >> 6)) * A_TILE_B + swo));
        float hprev = hp_hi + hp_lo;
        float rg = 1.f / (1.f + __expf(-(gr + bih[u * 3 + 0] + ar + bhh[u * 3 + 0])));
        float zg = 1.f / (1.f + __expf(-(gz + bih[u * 3 + 1] + az + bhh[u * 3 + 1])));
        float ng = tanhf(gn + bih[u * 3 + 2] + rg * (an + bhh[u * 3 + 2]));
        float hn = (1.f - zg) * ng + zg * hprev;
        __nv_bfloat16 hi = __float2bfloat16(hn);
        __nv_bfloat16 lo = __float2bfloat16(hn - __bfloat162float(hi));
        *(__nv_bfloat16*)((char*)hdst + (size_t)(u >> 6) * A_TILE_B + swo)        = hi;
        *(__nv_bfloat16*)((char*)hdst + (size_t)(32 + (u >> 6)) * A_TILE_B + swo) = hi;
        *(__nv_bfloat16*)((char*)hdst + (size_t)(16 + (u >> 6)) * A_TILE_B + swo) = lo;
        if (mode) fcsum += hn * fcW[u];
    }
    if (mode) {
        fcsum += __shfl_down_sync(0xffffffffu, fcsum, 2, 4);
        fcsum += __shfl_down_sync(0xffffffffu, fcsum, 1, 4);
        if (uq == 0) atomicAdd(&dout[b * TLEN + t], fcsum);
    }
}

// ---------------- host launch ----------------
extern "C" void kernel_launch(void* const* d_in, const int* in_sizes, int n_in,
                              void* d_out, int out_size) {
    const float* x    = (const float*)d_in[0];
    const float* eWih = (const float*)d_in[1];
    const float* eWhh = (const float*)d_in[2];
    const float* ebih = (const float*)d_in[3];
    const float* ebhh = (const float*)d_in[4];
    const float* dWih = (const float*)d_in[5];
    const float* dWhh = (const float*)d_in[6];
    const float* dbih = (const float*)d_in[7];
    const float* dbhh = (const float*)d_in[8];
    const float* fcW  = (const float*)d_in[9];
    const float* fcb  = (const float*)d_in[10];
    float* out = (float*)d_out;

    cudaFuncSetAttribute(gru_step_kernel,
                         cudaFuncAttributeMaxDynamicSharedMemorySize, SMEMSZ);

    prep_weights<<<(unsigned)((2 * (size_t)N3 * KK + 255) / 256), 256>>>(eWhh, dWhh);
    prep_misc<<<1024, 256>>>(ebih, ebhh, dbih, dbhh, eWih, dWih, fcb, out);

    dim3 grid(N3 / 48, BB / 32);   // (64, 8) = 512 CTAs -> 4 per SM
    for (int t = 0; t < TT; t++)
        gru_step_kernel<<<grid, 128, SMEMSZ>>>(t, 0, t & 1, x, fcW, out);
    for (int s = 0; s < TLEN; s++)
        gru_step_kernel<<<grid, 128, SMEMSZ>>>(s, 1, s & 1, x, fcW, out);
}

// round 17
// speedup vs baseline: 1.7245x; 1.7245x over previous
#include <cuda_runtime.h>
#include <cuda_bf16.h>
#include <cuda_fp16.h>
#include <cstdint>

#define BB 256   // batch
#define TT 512   // encoder steps
#define FF 64    // input features
#define HH 1024  // hidden
#define TLEN 64  // decoder steps
#define N3 3072  // 3*H output columns (gate-interleaved)
#define NC 16    // K chunks of 64 (K = 1024, single fp16 precision)
#define NSTG 4   // pipeline stages (power of 2)

#define A_TILE_B 8192           // h tile: 64 rows x 128B (SW128)
#define B_TILE_B 6144           // W tile: 48 rows x 128B
#define STAGE_B  (A_TILE_B + B_TILE_B)   // 14336
#define HDR 1024
#define SMEMSZ (HDR + NSTG * STAGE_B)    // 58368  -> 2 CTAs/SM

__device__ __forceinline__ uint32_t sw128(uint32_t off) { return off ^ ((off >> 3) & 0x70); }

// ---------------- device scratch (static globals; no allocation) ----------------
// Weights as contiguous pre-swizzled fp16 tiles: [2][64 nb][16 c][48*64]
__device__ __align__(128) __half g_Wt[2][64][NC][48 * 64];          // 12.6 MB
// h as contiguous pre-swizzled fp16 tiles: [2 par][4 mb][16 c][64*64]
__device__ __align__(128) __half g_ht[2][4][NC][64 * 64];           // 1 MB
// exact fp32 h mirror (carried state): [2 par][4 mb][64 row][1024 u]
__device__ float g_hf[2][4][64][HH];                                // 2 MB
__device__ float g_bih_e[N3], g_bhh_e[N3], g_bih_d[N3], g_bhh_d[N3]; // permuted biases
__device__ float g_Wihp_e[(size_t)HH * 192];            // enc W_ih, per-unit [r|z|n]
__device__ float g_Wih_d[N3];                           // dec W_ih (scalar input), permuted

// ---------------- PTX helpers ----------------
__device__ __forceinline__ void ldsm_x4(uint32_t* r, uint32_t addr) {
    asm volatile("ldmatrix.sync.aligned.m8n8.x4.shared.b16 {%0,%1,%2,%3}, [%4];"
                 : "=r"(r[0]), "=r"(r[1]), "=r"(r[2]), "=r"(r[3]) : "r"(addr));
}
__device__ __forceinline__ void ldsm_x2(uint32_t* r, uint32_t addr) {
    asm volatile("ldmatrix.sync.aligned.m8n8.x2.shared.b16 {%0,%1}, [%2];"
                 : "=r"(r[0]), "=r"(r[1]) : "r"(addr));
}
__device__ __forceinline__ void mma_f16(float* c, const uint32_t* a, uint32_t b0, uint32_t b1) {
    asm volatile("mma.sync.aligned.m16n8k16.row.col.f32.f16.f16.f32 "
                 "{%0,%1,%2,%3}, {%4,%5,%6,%7}, {%8,%9}, {%0,%1,%2,%3};"
                 : "+f"(c[0]), "+f"(c[1]), "+f"(c[2]), "+f"(c[3])
                 : "r"(a[0]), "r"(a[1]), "r"(a[2]), "r"(a[3]), "r"(b0), "r"(b1));
}
__device__ __forceinline__ void mbar_init(uint32_t mbar, uint32_t cnt) {
    asm volatile("mbarrier.init.shared.b64 [%0], %1;" :: "r"(mbar), "r"(cnt) : "memory");
}
__device__ __forceinline__ void mbar_expect_tx(uint32_t mbar, uint32_t bytes) {
    asm volatile("mbarrier.arrive.expect_tx.shared.b64 _, [%0], %1;"
                 :: "r"(mbar), "r"(bytes) : "memory");
}
__device__ __forceinline__ void mbar_wait(uint32_t mbar, uint32_t parity) {
    asm volatile(
        "{\n\t.reg .pred P1;\n\t"
        "WL_%=:\n\t"
        "mbarrier.try_wait.parity.acquire.cta.shared::cta.b64 P1, [%0], %1, 0x989680;\n\t"
        "@P1 bra.uni WD_%=;\n\t"
        "bra.uni WL_%=;\n\t"
        "WD_%=:\n\t}"
        :: "r"(mbar), "r"(parity) : "memory");
}
__device__ __forceinline__ void bulk_g2s(uint32_t dst, const void* src, uint32_t bytes, uint32_t mbar) {
    asm volatile("cp.async.bulk.shared::cluster.global.mbarrier::complete_tx::bytes "
                 "[%0], [%1], %2, [%3];"
                 :: "r"(dst), "l"(src), "r"(bytes), "r"(mbar) : "memory");
}

// ---------------- prep: tiled, swizzled, gate-interleaved fp16 weights ----------------
// permuted col j = 3u+g; tile nb = j/48, row jr = j%48; K = 1024 (16 chunks of 64)
__global__ void prep_weights(const float* __restrict__ encW, const float* __restrict__ decW) {
    size_t idx = (size_t)blockIdx.x * blockDim.x + threadIdx.x;
    const size_t one = (size_t)N3 * HH;
    if (idx >= 2 * one) return;
    int which = idx >= one;
    size_t rem = which ? idx - one : idx;
    int j = (int)(rem / HH);
    int k = (int)(rem % HH);
    int u = j / 3, g = j - 3 * u;
    const float* W = which ? decW : encW;
    float w = W[(size_t)(g * HH + u) * HH + k];
    int nb = j / 48, jr = j - nb * 48;
    int c = k >> 6, kk = k & 63;
    uint32_t swb = sw128((uint32_t)(jr * 128 + kk * 2));
    g_Wt[which][nb][c][swb >> 1] = __float2half(w);
}

// ---------------- prep: biases, permuted W_ih, zero h, init d_out = fc_b ----------------
__global__ void prep_misc(const float* __restrict__ ebih, const float* __restrict__ ebhh,
                          const float* __restrict__ dbih, const float* __restrict__ dbhh,
                          const float* __restrict__ eWih, const float* __restrict__ dWih,
                          const float* __restrict__ fcb, float* __restrict__ dout) {
    int tid = blockIdx.x * blockDim.x + threadIdx.x;
    int stride = gridDim.x * blockDim.x;
    for (int i = tid; i < N3; i += stride) {
        int u = i / 3, g = i - 3 * u;
        int o = g * HH + u;
        g_bih_e[i] = ebih[o];
        g_bhh_e[i] = ebhh[o];
        g_bih_d[i] = dbih[o];
        g_bhh_d[i] = dbhh[o];
        g_Wih_d[i] = dWih[o];
    }
    for (int i = tid; i < HH * 192; i += stride) {
        int u = i / 192, rem = i - u * 192;
        int g = rem >> 6, f = rem & 63;
        g_Wihp_e[i] = eWih[(size_t)(g * HH + u) * FF + f];
    }
    const int nh = 2 * 4 * NC * 64 * 64 / 2;    // u32 words over both fp16 h buffers
    for (int i = tid; i < nh; i += stride) ((uint32_t*)g_ht)[i] = 0u;
    const int nf = 2 * 4 * 64 * HH;             // fp32 mirror
    for (int i = tid; i < nf; i += stride) ((float*)g_hf)[i] = 0.f;
    for (int i = tid; i < BB * TLEN; i += stride) dout[i] = fcb[0];
}

// ---------------- one recurrent step: 2-CTA/SM fp16 GEMM + fused GRU epilogue ----------------
// grid (64, 4): blockIdx.x = 48-col tile (16 units), blockIdx.y = 64-row batch tile.
// 128 threads, 4 warps as 2(M) x 2(N), warp tile 32x24.
__global__ __launch_bounds__(128, 2) void gru_step_kernel(
    int t, int mode, int par,
    const float* __restrict__ x, const float* __restrict__ fcW, float* __restrict__ dout)
{
    const float* __restrict__ bih = mode ? g_bih_d : g_bih_e;
    const float* __restrict__ bhh = mode ? g_bhh_d : g_bhh_e;

    extern __shared__ __align__(16) unsigned char smem_raw[];
    const int tid = threadIdx.x;
    const int lane = tid & 31, warp = tid >> 5;
    const int wm = warp >> 1, wn = warp & 1;     // 2 x 2 warps -> 32x24 warp tiles
    const int nb = blockIdx.x, mb = blockIdx.y;

    const uint32_t smBase = (uint32_t)__cvta_generic_to_shared(smem_raw);
    const uint32_t mbar0 = smBase;               // 4 mbarriers x 8B in header
    const uint32_t smData = smBase + HDR;

    const __half* __restrict__ Asrc = &g_ht[par][mb][0][0];
    const __half* __restrict__ Bsrc = &g_Wt[mode][nb][0][0];
    __half* __restrict__ htd = &g_ht[par ^ 1][mb][0][0];
    float* __restrict__ hfd = &g_hf[par ^ 1][mb][0][0];
    const float* __restrict__ hfs = &g_hf[par][mb][0][0];

    if (tid == 0) {
        #pragma unroll
        for (int s = 0; s < NSTG; s++) mbar_init(mbar0 + 8 * s, 1);
    }
    __syncthreads();

    auto issue = [&](int c) {
        const int s = c & (NSTG - 1);
        const uint32_t mb_ = mbar0 + 8 * s;
        mbar_expect_tx(mb_, STAGE_B);
        const uint32_t d = smData + s * STAGE_B;
        bulk_g2s(d,            Asrc + (size_t)c * 4096, A_TILE_B, mb_);
        bulk_g2s(d + A_TILE_B, Bsrc + (size_t)c * 3072, B_TILE_B, mb_);
    };

    if (tid == 0) {
        #pragma unroll
        for (int s = 0; s < NSTG - 1; s++) issue(s);
    }

    float acc[2][3][4];
    #pragma unroll
    for (int mi = 0; mi < 2; mi++)
        #pragma unroll
        for (int ni = 0; ni < 3; ni++)
            #pragma unroll
            for (int q = 0; q < 4; q++) acc[mi][ni][q] = 0.f;

    for (int c = 0; c < NC; c++) {
        __syncthreads();                          // previous stage slot drained by all warps
        if (tid == 0 && c + NSTG - 1 < NC) issue(c + NSTG - 1);
        mbar_wait(mbar0 + 8 * (c & (NSTG - 1)), (c >> 2) & 1);

        const uint32_t sA = smData + (c & (NSTG - 1)) * STAGE_B;
        const uint32_t sB = sA + A_TILE_B;
        #pragma unroll
        for (int ks = 0; ks < 4; ks++) {
            uint32_t ra[2][4], rb4[4], rb2[2];
            #pragma unroll
            for (int mi = 0; mi < 2; mi++) {
                uint32_t off = (uint32_t)((wm * 32 + mi * 16 + (lane & 15)) * 128
                                          + ks * 32 + (lane >> 4) * 16);
                ldsm_x4(ra[mi], sA + sw128(off));
            }
            {   // B n16k16 via one x4 (rows wn*24 .. +15)
                uint32_t off = (uint32_t)((wn * 24 + (lane & 15)) * 128
                                          + ks * 32 + (lane >> 4) * 16);
                ldsm_x4(rb4, sB + sw128(off));
            }
            {   // B n8k16 via x2 (rows wn*24+16 .. +23)
                uint32_t off = (uint32_t)((wn * 24 + 16 + (lane & 7)) * 128
                                          + ks * 32 + ((lane >> 3) & 1) * 16);
                ldsm_x2(rb2, sB + sw128(off));
            }
            // x4 B reg order: {n0-7 k0-7, n8-15 k0-7, n0-7 k8-15, n8-15 k8-15}
            #pragma unroll
            for (int mi = 0; mi < 2; mi++) {
                mma_f16(acc[mi][0], ra[mi], rb4[0], rb4[2]);
                mma_f16(acc[mi][1], ra[mi], rb4[1], rb4[3]);
                mma_f16(acc[mi][2], ra[mi], rb2[0], rb2[1]);
            }
        }
    }

    // ---- stage accumulators to smem (reuse data region) ----
    __syncthreads();
    float* Csm = (float*)(smem_raw + HDR);               // 64 x 48, pitch 51 (13056 B)
    float* Xs  = (float*)(smem_raw + HDR + 13312);       // 64 x 64 floats (16384 B)
    #pragma unroll
    for (int mi = 0; mi < 2; mi++)
        #pragma unroll
        for (int ni = 0; ni < 3; ni++) {
            int m = wm * 32 + mi * 16 + (lane >> 2);
            int n = wn * 24 + ni * 8 + ((lane & 3) << 1);
            Csm[m * 51 + n]           = acc[mi][ni][0];
            Csm[m * 51 + n + 1]       = acc[mi][ni][1];
            Csm[(m + 8) * 51 + n]     = acc[mi][ni][2];
            Csm[(m + 8) * 51 + n + 1] = acc[mi][ni][3];
        }
    if (mode == 0) {
        #pragma unroll
        for (int q = 0; q < 8; q++) {
            int id = tid + q * 128;
            int r = id >> 4, c4 = id & 15;
            ((float4*)Xs)[r * 16 + c4] =
                *(const float4*)(x + ((size_t)(mb * 64 + r) * TT + t) * FF + c4 * 4);
        }
    }
    __syncthreads();

    // ---- fused GRU epilogue: each thread owns (batch row bl, 8 hidden units) ----
    const int bl = tid >> 1, uq = tid & 1;
    const int b = mb * 64 + bl;
    float inp = 0.f;
    if (mode && t > 0) inp = dout[b * TLEN + (t - 1)];
    float fcsum = 0.f;
    const float4* xs4 = (const float4*)(Xs + bl * 64);

    #pragma unroll
    for (int i = 0; i < 8; i++) {
        int ul = uq * 8 + i;
        int u = nb * 16 + ul;
        float ar = Csm[bl * 51 + ul * 3 + 0];
        float az = Csm[bl * 51 + ul * 3 + 1];
        float an = Csm[bl * 51 + ul * 3 + 2];
        float gr, gz, gn;
        if (mode == 0) {
            gr = gz = gn = 0.f;
            const float4* wr4 = (const float4*)(g_Wihp_e + (size_t)u * 192);
            #pragma unroll
            for (int q = 0; q < 16; q++) {
                float4 xv = xs4[q];
                float4 a = wr4[q], bq = wr4[16 + q], cq = wr4[32 + q];
                gr += xv.x * a.x + xv.y * a.y + xv.z * a.z + xv.w * a.w;
                gz += xv.x * bq.x + xv.y * bq.y + xv.z * bq.z + xv.w * bq.w;
                gn += xv.x * cq.x + xv.y * cq.y + xv.z * cq.z + xv.w * cq.w;
            }
        } else {
            gr = inp * g_Wih_d[u * 3 + 0];
            gz = inp * g_Wih_d[u * 3 + 1];
            gn = inp * g_Wih_d[u * 3 + 2];
        }
        float hprev = hfs[(size_t)bl * HH + u];  // exact fp32 carried state
        float rg = 1.f / (1.f + __expf(-(gr + bih[u * 3 + 0] + ar + bhh[u * 3 + 0])));
        float zg = 1.f / (1.f + __expf(-(gz + bih[u * 3 + 1] + az + bhh[u * 3 + 1])));
        float ng = tanhf(gn + bih[u * 3 + 2] + rg * (an + bhh[u * 3 + 2]));
        float hn = (1.f - zg) * ng + zg * hprev;
        // fp16 GEMM operand + fp32 mirror
        const int kk2 = (u & 63) * 2;
        const uint32_t swo = sw128((uint32_t)(bl * 128 + kk2));
        *(__half*)((char*)htd + (size_t)(u >> 6) * A_TILE_B + swo) = __float2half(hn);
        hfd[(size_t)bl * HH + u] = hn;
        if (mode) fcsum += hn * fcW[u];
    }
    if (mode) {
        fcsum += __shfl_down_sync(0xffffffffu, fcsum, 1, 2);
        if (uq == 0) atomicAdd(&dout[b * TLEN + t], fcsum);
    }
}

// ---------------- host launch ----------------
extern "C" void kernel_launch(void* const* d_in, const int* in_sizes, int n_in,
                              void* d_out, int out_size) {
    const float* x    = (const float*)d_in[0];
    const float* eWih = (const float*)d_in[1];
    const float* eWhh = (const float*)d_in[2];
    const float* ebih = (const float*)d_in[3];
    const float* ebhh = (const float*)d_in[4];
    const float* dWih = (const float*)d_in[5];
    const float* dWhh = (const float*)d_in[6];
    const float* dbih = (const float*)d_in[7];
    const float* dbhh = (const float*)d_in[8];
    const float* fcW  = (const float*)d_in[9];
    const float* fcb  = (const float*)d_in[10];
    float* out = (float*)d_out;

    cudaFuncSetAttribute(gru_step_kernel,
                         cudaFuncAttributeMaxDynamicSharedMemorySize, SMEMSZ);

    prep_weights<<<(unsigned)((2 * (size_t)N3 * HH + 255) / 256), 256>>>(eWhh, dWhh);
    prep_misc<<<1024, 256>>>(ebih, ebhh, dbih, dbhh, eWih, dWih, fcb, out);

    dim3 grid(N3 / 48, BB / 64);   // (64, 4) = 256 CTAs -> 2 per SM
    for (int t = 0; t < TT; t++)
        gru_step_kernel<<<grid, 128, SMEMSZ>>>(t, 0, t & 1, x, fcW, out);
    for (int s = 0; s < TLEN; s++)
        gru_step_kernel<<<grid, 128, SMEMSZ>>>(s, 1, s & 1, x, fcW, out);
}